// round 10
// baseline (speedup 1.0000x reference)
#include <cuda_runtime.h>
#include <math.h>
#include <stdint.h>

#define T_STEPS 512
#define BATCH   64
#define IN_DIM  1024
#define HID     1024
#define BH      (BATCH * HID)          // 65536

// ---------- TF32 helpers ----------
__device__ __forceinline__ uint32_t f2tf32(float f) {
    uint32_t r;
    asm("cvt.rna.tf32.f32 %0, %1;" : "=r"(r) : "f"(f));
    return r;
}

__device__ __forceinline__ float tanh_fast(float x) {
    float y;
    asm("tanh.approx.f32 %0, %1;" : "=f"(y) : "f"(x));
    return y;
}

__device__ __forceinline__ void mma_tf32(float c[4], const uint32_t a[4], const uint32_t b[2]) {
    asm("mma.sync.aligned.m16n8k8.row.col.f32.tf32.tf32.f32 "
        "{%0,%1,%2,%3}, {%4,%5,%6,%7}, {%8,%9}, {%0,%1,%2,%3};\n"
        : "+f"(c[0]), "+f"(c[1]), "+f"(c[2]), "+f"(c[3])
        : "r"(a[0]), "r"(a[1]), "r"(a[2]), "r"(a[3]), "r"(b[0]), "r"(b[1]));
}

__device__ __forceinline__ unsigned ld_relaxed(const unsigned* p) {
    unsigned v;
    asm volatile("ld.relaxed.gpu.global.u32 %0, [%1];" : "=r"(v) : "l"(p) : "memory");
    return v;
}

__device__ __forceinline__ void red_release(unsigned* p) {
    asm volatile("red.release.gpu.global.add.u32 [%0], %1;" :: "l"(p), "r"(1u) : "memory");
}

// ============================================================
// Kernel 1: Xp = X @ W_xh + b  (TF32 mma, pre-converted smem) — unchanged.
// ============================================================
#define XA_STRIDE 36
#define XB_STRIDE 72

__global__ __launch_bounds__(256) void xp_gemm_tf32(const float* __restrict__ A,
                                                    const float* __restrict__ B,
                                                    const float* __restrict__ bias,
                                                    float* __restrict__ C) {
    __shared__ uint32_t As[128][XA_STRIDE];
    __shared__ uint32_t Bs[32][XB_STRIDE];
    __shared__ float biasS[64];

    const int bm  = blockIdx.y * 128;
    const int bn  = blockIdx.x * 64;
    const int tid = threadIdx.x;
    const int wid = tid >> 5;
    const int lane = tid & 31;
    const int gr  = lane >> 2;
    const int tg  = lane & 3;
    const int m_warp = wid & 1;
    const int n_warp = wid >> 1;

    if (tid < 64) biasS[tid] = bias[bn + tid];

    float acc[4][2][4] = {};

    for (int k0 = 0; k0 < IN_DIM; k0 += 32) {
        #pragma unroll
        for (int j = 0; j < 4; j++) {
            int idx = tid + j * 256;
            int m   = idx >> 3;
            int kq  = (idx & 7) * 4;
            float4 v = *reinterpret_cast<const float4*>(
                &A[(size_t)(bm + m) * IN_DIM + k0 + kq]);
            uint4 w = make_uint4(f2tf32(v.x), f2tf32(v.y), f2tf32(v.z), f2tf32(v.w));
            *reinterpret_cast<uint4*>(&As[m][kq]) = w;
        }
        #pragma unroll
        for (int j = 0; j < 2; j++) {
            int idx = tid + j * 256;
            int kk  = idx >> 4;
            int nq  = (idx & 15) * 4;
            float4 v = *reinterpret_cast<const float4*>(
                &B[(size_t)(k0 + kk) * HID + bn + nq]);
            uint4 w = make_uint4(f2tf32(v.x), f2tf32(v.y), f2tf32(v.z), f2tf32(v.w));
            *reinterpret_cast<uint4*>(&Bs[kk][nq]) = w;
        }
        __syncthreads();

        #pragma unroll
        for (int ks = 0; ks < 4; ks++) {
            const int k8 = ks * 8;
            uint32_t bf[2][2];
            #pragma unroll
            for (int nt = 0; nt < 2; nt++) {
                int nn = n_warp * 16 + nt * 8 + gr;
                bf[nt][0] = Bs[k8 + tg][nn];
                bf[nt][1] = Bs[k8 + tg + 4][nn];
            }
            #pragma unroll
            for (int mt = 0; mt < 4; mt++) {
                int mb = m_warp * 64 + mt * 16;
                uint32_t af[4];
                af[0] = As[mb + gr][k8 + tg];
                af[1] = As[mb + gr + 8][k8 + tg];
                af[2] = As[mb + gr][k8 + tg + 4];
                af[3] = As[mb + gr + 8][k8 + tg + 4];
                mma_tf32(acc[mt][0], af, bf[0]);
                mma_tf32(acc[mt][1], af, bf[1]);
            }
        }
        __syncthreads();
    }

    #pragma unroll
    for (int mt = 0; mt < 4; mt++) {
        #pragma unroll
        for (int nt = 0; nt < 2; nt++) {
            int colL = n_warp * 16 + nt * 8 + 2 * tg;
            int row0 = bm + m_warp * 64 + mt * 16 + gr;
            float2 v0, v1;
            v0.x = acc[mt][nt][0] + biasS[colL];
            v0.y = acc[mt][nt][1] + biasS[colL + 1];
            v1.x = acc[mt][nt][2] + biasS[colL];
            v1.y = acc[mt][nt][3] + biasS[colL + 1];
            *reinterpret_cast<float2*>(&C[(size_t)row0 * HID + bn + colL]) = v0;
            *reinterpret_cast<float2*>(&C[(size_t)(row0 + 8) * HID + bn + colL]) = v1;
        }
    }
}

// ============================================================
// Persistent scan v3: FULL-K per block. 32 blocks x 32 cols.
// One wait + one flag per step. No global partials.
// Warp (mi,ni): 16m x 16n tile, K=1024.
// W_hh block slice pre-swizzled into fragment-order smem at init.
// h staged in 8 x 32KB double-buffered chunks.
// ============================================================
#define SC_BLOCKS 32
#define HS_STRIDE 144                       // words; 144 mod 32 == 16
#define HS_WORDS  (64 * HS_STRIDE)          // 9216 words / buffer
#define SMEM_BYTES (2 * HS_WORDS * 4 + 2 * 2 * 64 * 32 * 16)  // 73728 + 131072 = 204800
#define FSTRIDE   32

__device__ unsigned g_flag[SC_BLOCKS * FSTRIDE];
__device__ unsigned g_done = 0;

__device__ __forceinline__ void warp_wait_all(const unsigned* flags, unsigned tgt) {
    const int lane = threadIdx.x & 31;
    const unsigned* a = &flags[lane * FSTRIDE];
    int spins = 0;
    bool done = false;
    while (true) {
        if (!done) done = (ld_relaxed(a) >= tgt);
        if (__ballot_sync(0xffffffffu, !done) == 0) break;
        if (++spins > 8192) __nanosleep(64);
    }
    asm volatile("fence.acq_rel.gpu;" ::: "memory");
}

__global__ __launch_bounds__(256, 1) void rnn_scan(const float* __restrict__ W,
                                                   float* __restrict__ out) {
    extern __shared__ uint32_t smem[];
    uint32_t* hs0 = smem;
    uint32_t* hs1 = smem + HS_WORDS;
    uint4*    Bf  = reinterpret_cast<uint4*>(smem + 2 * HS_WORDS);
    // Bf layout: [ni(2)][nt(2)][u(64)][lane(32)] uint4 — lane-indexed, conflict-free.

    const int tid  = threadIdx.x;
    const int bid  = blockIdx.x;
    const int wid  = tid >> 5;
    const int lane = tid & 31;
    const int gr   = lane >> 2;
    const int tg   = lane & 3;
    const int mi   = wid >> 1;           // 0..3  (16-row tile)
    const int ni   = wid & 1;            // 0..1  (16-col tile)
    const int n_base = bid * 32;

    // ---- Init: W_hh fragments into smem, fragment order.  Warp (mi,ni)
    //      covers u in [16*mi, 16*mi+16) for its ni group (4 warps share
    //      each ni group; mi splits the u range). ----
    #pragma unroll 4
    for (int u = mi * 16; u < mi * 16 + 16; u++) {
        #pragma unroll
        for (int nt = 0; nt < 2; nt++) {
            int n  = n_base + ni * 16 + nt * 8 + gr;
            int k0 = 16 * u + 4 * tg;
            uint4 v;
            v.x = f2tf32(W[(size_t)(k0 + 0) * HID + n]);
            v.y = f2tf32(W[(size_t)(k0 + 1) * HID + n]);
            v.z = f2tf32(W[(size_t)(k0 + 2) * HID + n]);
            v.w = f2tf32(W[(size_t)(k0 + 3) * HID + n]);
            Bf[(((ni * 2 + nt) * 64) + u) * 32 + lane] = v;
        }
    }
    __syncthreads();

    // ---- Step 0: h_0 = tanh(Xp_0) over my 32-col slice ----
    #pragma unroll
    for (int j = 0; j < 2; j++) {
        int idx = tid + j * 256;            // 0..511
        int b   = idx >> 3;                 // 0..63
        int c4  = (idx & 7) * 4;            // 0..28
        float4 v = *reinterpret_cast<float4*>(&out[(size_t)b * HID + n_base + c4]);
        v.x = tanh_fast(v.x); v.y = tanh_fast(v.y);
        v.z = tanh_fast(v.z); v.w = tanh_fast(v.w);
        *reinterpret_cast<float4*>(&out[(size_t)b * HID + n_base + c4]) = v;
    }
    __syncthreads();
    if (tid == 0) red_release(&g_flag[bid * FSTRIDE]);   // flag = 1

    const int rowA = mi * 16 + gr;

    for (int t = 1; t < T_STEPS; t++) {
        const float* h = out + (size_t)(t - 1) * BH;
        float* o       = out + (size_t)t * BH;

        // ---- Single wait: all 32 blocks have written out[t-1] ----
        if (wid == 0) warp_wait_all(g_flag, (unsigned)t);
        __syncthreads();

        // ---- Load chunk 0 into registers ----
        float4 rr[8];
        #pragma unroll
        for (int j = 0; j < 8; j++) {
            int idx = tid + j * 256;
            int b   = idx >> 5;
            int kq  = (idx & 31) * 4;
            rr[j] = *reinterpret_cast<const float4*>(&h[(size_t)b * HID + kq]);
        }

        // ---- Prefetch Xp for my outputs (written only by me — race-free) ----
        float2 xp[2][2];
        #pragma unroll
        for (int nt = 0; nt < 2; nt++) {
            int col = n_base + ni * 16 + nt * 8 + 2 * tg;
            xp[nt][0] = *reinterpret_cast<const float2*>(&o[(size_t)rowA * HID + col]);
            xp[nt][1] = *reinterpret_cast<const float2*>(&o[(size_t)(rowA + 8) * HID + col]);
        }

        float acc[2][4] = {};

        #pragma unroll
        for (int c = 0; c < 8; c++) {
            uint32_t* hb = (c & 1) ? hs1 : hs0;

            // Store staged chunk (cvt to tf32)
            #pragma unroll
            for (int j = 0; j < 8; j++) {
                int idx = tid + j * 256;
                int b   = idx >> 5;
                int kq  = (idx & 31) * 4;
                uint4 w = make_uint4(f2tf32(rr[j].x), f2tf32(rr[j].y),
                                     f2tf32(rr[j].z), f2tf32(rr[j].w));
                *reinterpret_cast<uint4*>(&hb[b * HS_STRIDE + kq]) = w;
            }
            __syncthreads();

            // Issue loads for next chunk (overlaps mma below)
            if (c < 7) {
                #pragma unroll
                for (int j = 0; j < 8; j++) {
                    int idx = tid + j * 256;
                    int b   = idx >> 5;
                    int kq  = (idx & 31) * 4;
                    rr[j] = *reinterpret_cast<const float4*>(
                        &h[(size_t)b * HID + 128 * (c + 1) + kq]);
                }
            }

            // mma over this chunk: 8 u-steps x 2 n-tiles x 2 = 32 mma
            #pragma unroll
            for (int u8 = 0; u8 < 8; u8++) {
                const int kc = 16 * u8 + 4 * tg;
                uint4 va = *reinterpret_cast<const uint4*>(&hb[rowA * HS_STRIDE + kc]);
                uint4 vb = *reinterpret_cast<const uint4*>(&hb[(rowA + 8) * HS_STRIDE + kc]);
                uint32_t afA[4] = {va.x, vb.x, va.y, vb.y};
                uint32_t afB[4] = {va.z, vb.z, va.w, vb.w};
                const int u = c * 8 + u8;
                #pragma unroll
                for (int nt = 0; nt < 2; nt++) {
                    uint4 b4 = Bf[(((ni * 2 + nt) * 64) + u) * 32 + lane];
                    uint32_t bfA[2] = {b4.x, b4.y};
                    uint32_t bfB[2] = {b4.z, b4.w};
                    mma_tf32(acc[nt], afA, bfA);
                    mma_tf32(acc[nt], afB, bfB);
                }
            }
            __syncthreads();
        }

        // ---- Epilogue: add Xp, tanh, write out[t] (my region) ----
        #pragma unroll
        for (int nt = 0; nt < 2; nt++) {
            int col = n_base + ni * 16 + nt * 8 + 2 * tg;
            float2 v0, v1;
            v0.x = tanh_fast(acc[nt][0] + xp[nt][0].x);
            v0.y = tanh_fast(acc[nt][1] + xp[nt][0].y);
            v1.x = tanh_fast(acc[nt][2] + xp[nt][1].x);
            v1.y = tanh_fast(acc[nt][3] + xp[nt][1].y);
            *reinterpret_cast<float2*>(&o[(size_t)rowA * HID + col]) = v0;
            *reinterpret_cast<float2*>(&o[(size_t)(rowA + 8) * HID + col]) = v1;
            if (t == T_STEPS - 1) {   // fused final-state tail copy
                float* tail = out + (size_t)T_STEPS * BH;
                *reinterpret_cast<float2*>(&tail[(size_t)rowA * HID + col]) = v0;
                *reinterpret_cast<float2*>(&tail[(size_t)(rowA + 8) * HID + col]) = v1;
            }
        }
        __syncthreads();
        if (tid == 0) red_release(&g_flag[bid * FSTRIDE]);   // flag = t+1
    }

    // ---- Reset flags for graph replays ----
    __syncthreads();
    if (tid == 0) {
        unsigned d = atomicAdd(&g_done, 1u);
        if (d == (unsigned)(gridDim.x - 1)) {
            for (int i = 0; i < SC_BLOCKS; i++) g_flag[i * FSTRIDE] = 0;
            g_done = 0;
            __threadfence();
        }
    }
}

// ============================================================
extern "C" void kernel_launch(void* const* d_in, const int* in_sizes, int n_in,
                              void* d_out, int out_size) {
    const float* X    = (const float*)d_in[0];
    const float* W_xh = (const float*)d_in[1];
    const float* W_hh = (const float*)d_in[2];
    const float* b_h  = (const float*)d_in[3];
    float* out = (float*)d_out;

    {
        dim3 grid(HID / 64, (T_STEPS * BATCH) / 128);
        xp_gemm_tf32<<<grid, 256>>>(X, W_xh, b_h, out);
    }

    cudaFuncSetAttribute(rnn_scan, cudaFuncAttributeMaxDynamicSharedMemorySize,
                         SMEM_BYTES);
    rnn_scan<<<SC_BLOCKS, 256, SMEM_BYTES>>>(W_hh, out);
}

// round 11
// speedup vs baseline: 2.2820x; 2.2820x over previous
#include <cuda_runtime.h>
#include <math.h>
#include <stdint.h>

#define T_STEPS 512
#define BATCH   64
#define IN_DIM  1024
#define HID     1024
#define BH      (BATCH * HID)          // 65536

// ---------- TF32 helpers ----------
__device__ __forceinline__ uint32_t f2tf32(float f) {
    uint32_t r;
    asm("cvt.rna.tf32.f32 %0, %1;" : "=r"(r) : "f"(f));
    return r;
}

__device__ __forceinline__ float tanh_fast(float x) {
    float y;
    asm("tanh.approx.f32 %0, %1;" : "=f"(y) : "f"(x));
    return y;
}

__device__ __forceinline__ void mma_tf32(float c[4], const uint32_t a[4], const uint32_t b[2]) {
    asm("mma.sync.aligned.m16n8k8.row.col.f32.tf32.tf32.f32 "
        "{%0,%1,%2,%3}, {%4,%5,%6,%7}, {%8,%9}, {%0,%1,%2,%3};\n"
        : "+f"(c[0]), "+f"(c[1]), "+f"(c[2]), "+f"(c[3])
        : "r"(a[0]), "r"(a[1]), "r"(a[2]), "r"(a[3]), "r"(b[0]), "r"(b[1]));
}

__device__ __forceinline__ unsigned ld_relaxed(const unsigned* p) {
    unsigned v;
    asm volatile("ld.relaxed.gpu.global.u32 %0, [%1];" : "=r"(v) : "l"(p) : "memory");
    return v;
}

__device__ __forceinline__ void red_release(unsigned* p) {
    asm volatile("red.release.gpu.global.add.u32 [%0], %1;" :: "l"(p), "r"(1u) : "memory");
}

// ============================================================
// Kernel 1: Xp = X @ W_xh + b  (TF32 mma, pre-converted smem) — unchanged.
// ============================================================
#define XA_STRIDE 36
#define XB_STRIDE 72

__global__ __launch_bounds__(256) void xp_gemm_tf32(const float* __restrict__ A,
                                                    const float* __restrict__ B,
                                                    const float* __restrict__ bias,
                                                    float* __restrict__ C) {
    __shared__ uint32_t As[128][XA_STRIDE];
    __shared__ uint32_t Bs[32][XB_STRIDE];
    __shared__ float biasS[64];

    const int bm  = blockIdx.y * 128;
    const int bn  = blockIdx.x * 64;
    const int tid = threadIdx.x;
    const int wid = tid >> 5;
    const int lane = tid & 31;
    const int gr  = lane >> 2;
    const int tg  = lane & 3;
    const int m_warp = wid & 1;
    const int n_warp = wid >> 1;

    if (tid < 64) biasS[tid] = bias[bn + tid];

    float acc[4][2][4] = {};

    for (int k0 = 0; k0 < IN_DIM; k0 += 32) {
        #pragma unroll
        for (int j = 0; j < 4; j++) {
            int idx = tid + j * 256;
            int m   = idx >> 3;
            int kq  = (idx & 7) * 4;
            float4 v = *reinterpret_cast<const float4*>(
                &A[(size_t)(bm + m) * IN_DIM + k0 + kq]);
            uint4 w = make_uint4(f2tf32(v.x), f2tf32(v.y), f2tf32(v.z), f2tf32(v.w));
            *reinterpret_cast<uint4*>(&As[m][kq]) = w;
        }
        #pragma unroll
        for (int j = 0; j < 2; j++) {
            int idx = tid + j * 256;
            int kk  = idx >> 4;
            int nq  = (idx & 15) * 4;
            float4 v = *reinterpret_cast<const float4*>(
                &B[(size_t)(k0 + kk) * HID + bn + nq]);
            uint4 w = make_uint4(f2tf32(v.x), f2tf32(v.y), f2tf32(v.z), f2tf32(v.w));
            *reinterpret_cast<uint4*>(&Bs[kk][nq]) = w;
        }
        __syncthreads();

        #pragma unroll
        for (int ks = 0; ks < 4; ks++) {
            const int k8 = ks * 8;
            uint32_t bf[2][2];
            #pragma unroll
            for (int nt = 0; nt < 2; nt++) {
                int nn = n_warp * 16 + nt * 8 + gr;
                bf[nt][0] = Bs[k8 + tg][nn];
                bf[nt][1] = Bs[k8 + tg + 4][nn];
            }
            #pragma unroll
            for (int mt = 0; mt < 4; mt++) {
                int mb = m_warp * 64 + mt * 16;
                uint32_t af[4];
                af[0] = As[mb + gr][k8 + tg];
                af[1] = As[mb + gr + 8][k8 + tg];
                af[2] = As[mb + gr][k8 + tg + 4];
                af[3] = As[mb + gr + 8][k8 + tg + 4];
                mma_tf32(acc[mt][0], af, bf[0]);
                mma_tf32(acc[mt][1], af, bf[1]);
            }
        }
        __syncthreads();
    }

    #pragma unroll
    for (int mt = 0; mt < 4; mt++) {
        #pragma unroll
        for (int nt = 0; nt < 2; nt++) {
            int colL = n_warp * 16 + nt * 8 + 2 * tg;
            int row0 = bm + m_warp * 64 + mt * 16 + gr;
            float2 v0, v1;
            v0.x = acc[mt][nt][0] + biasS[colL];
            v0.y = acc[mt][nt][1] + biasS[colL + 1];
            v1.x = acc[mt][nt][2] + biasS[colL];
            v1.y = acc[mt][nt][3] + biasS[colL + 1];
            *reinterpret_cast<float2*>(&C[(size_t)row0 * HID + bn + colL]) = v0;
            *reinterpret_cast<float2*>(&C[(size_t)(row0 + 8) * HID + bn + colL]) = v1;
        }
    }
}

// ============================================================
// Persistent scan v4 — fused-reduce split-K, ONE global round/step.
// 128 blocks x 512 thr: (ks 8) x (nb 4) x (rh 4).
// Iter t: wait(flags>=t) -> deferred out[t-1] write -> stage h_t
// (Xp_t + sum of 8 partial buffers, tanh) into smem -> mma
// (W in 64 regs/thread) -> STG partials_{t+1} (parity) -> release.
// ============================================================
#define SC_BLOCKS 128
#define HS_STRIDE 144   // 144 mod 32 == 16 -> conflict-free LDS.128
#define FSTRIDE   32

__device__ float    g_part[2 * 8 * BH];    // 4 MB, parity-buffered partials
__device__ unsigned g_flag[SC_BLOCKS * FSTRIDE];
__device__ unsigned g_done = 0;

__global__ __launch_bounds__(512, 1) void rnn_scan(const float* __restrict__ W,
                                                   float* __restrict__ out) {
    __shared__ uint32_t hs[16][HS_STRIDE];   // staged h slice, tf32 bits

    const int tid  = threadIdx.x;
    const int bid  = blockIdx.x;
    const int ks   = bid >> 4;            // 0..7   k-slice
    const int nb   = (bid >> 2) & 3;      // 0..3   256-col group
    const int rh   = bid & 3;             // 0..3   16-row group
    const int wid  = tid >> 5;            // 0..15
    const int lane = tid & 31;
    const int gr   = lane >> 2;
    const int tg   = lane & 3;

    // ---- W_hh B-fragments in registers (64/thread), once for all steps ----
    // Warp wid covers cols [256nb + 16wid, +16). bfr[u][p][nt][i] =
    // W[128ks + 16u + 4tg + 2p + i][256nb + 16wid + 8nt + gr]  (R7 mapping)
    uint32_t bfr[8][2][2][2];
    {
        const int ncol = 256 * nb + 16 * wid;
        #pragma unroll
        for (int u = 0; u < 8; u++)
            #pragma unroll
            for (int p = 0; p < 2; p++)
                #pragma unroll
                for (int nt = 0; nt < 2; nt++) {
                    int n  = ncol + 8 * nt + gr;
                    int kk = 128 * ks + 16 * u + 4 * tg + 2 * p;
                    bfr[u][p][nt][0] = f2tf32(W[(size_t)kk * HID + n]);
                    bfr[u][p][nt][1] = f2tf32(W[(size_t)(kk + 1) * HID + n]);
                }
    }

    // ---- Per-thread staging slot: row r of staged region, 4 cols ----
    const int r   = tid >> 5;              // 0..15
    const int c4  = (tid & 31) * 4;        // 0..124
    const int g_row = 16 * rh + r;         // global batch row
    const size_t my_off = (size_t)g_row * HID + 128 * ks + c4;
    const bool owned = ((r >> 2) == nb);   // rows 4nb..4nb+3 of staged region
    float4 saved;                          // deferred fp32 h for out[]

    for (int t = 0; t < T_STEPS; t++) {
        float* o = out + (size_t)t * BH;

        // ---- Single wait: partials for h_t published by all blocks ----
        if (t > 0) {
            if (wid < 4) {
                const unsigned* a = &g_flag[(wid * 32 + lane) * FSTRIDE];
                int spins = 0;
                bool done = false;
                while (true) {
                    if (!done) done = (ld_relaxed(a) >= (unsigned)t);
                    if (__ballot_sync(0xffffffffu, !done) == 0) break;
                    if (++spins > 8192) __nanosleep(64);
                }
                asm volatile("fence.acq_rel.gpu;" ::: "memory");
            }
            __syncthreads();

            // Deferred write of out[t-1] (safe: everyone passed staging t-1)
            if (owned)
                *reinterpret_cast<float4*>(&out[(size_t)(t - 1) * BH + my_off]) = saved;
        }

        // ---- Stage h_t: Xp_t + sum of 8 partials, tanh -> smem ----
        {
            float4 s = *reinterpret_cast<const float4*>(&o[my_off]);   // Xp_t
            if (t > 0) {
                const float* pb = g_part + (size_t)(t & 1) * (8 * BH);
                #pragma unroll
                for (int kk = 0; kk < 8; kk++) {
                    float4 p = *reinterpret_cast<const float4*>(
                        &pb[(size_t)kk * BH + my_off]);
                    s.x += p.x; s.y += p.y; s.z += p.z; s.w += p.w;
                }
            }
            s.x = tanh_fast(s.x); s.y = tanh_fast(s.y);
            s.z = tanh_fast(s.z); s.w = tanh_fast(s.w);
            if (owned) saved = s;
            uint4 w = make_uint4(f2tf32(s.x), f2tf32(s.y), f2tf32(s.z), f2tf32(s.w));
            *reinterpret_cast<uint4*>(&hs[r][c4]) = w;
        }
        __syncthreads();

        // ---- Partial GEMM for step t+1 (skip on last step) ----
        if (t < T_STEPS - 1) {
            float acc[2][4] = {};
            #pragma unroll
            for (int u = 0; u < 8; u++) {
                const int kc = 16 * u + 4 * tg;
                uint4 va = *reinterpret_cast<const uint4*>(&hs[gr][kc]);
                uint4 vb = *reinterpret_cast<const uint4*>(&hs[gr + 8][kc]);
                uint32_t afA[4] = {va.x, vb.x, va.y, vb.y};
                uint32_t afB[4] = {va.z, vb.z, va.w, vb.w};
                mma_tf32(acc[0], afA, bfr[u][0][0]);
                mma_tf32(acc[1], afA, bfr[u][0][1]);
                mma_tf32(acc[0], afB, bfr[u][1][0]);
                mma_tf32(acc[1], afB, bfr[u][1][1]);
            }
            // Store partials to parity buffer (t+1)&1
            float* gp = g_part + (size_t)((t + 1) & 1) * (8 * BH) + (size_t)ks * BH;
            const int ncol = 256 * nb + 16 * wid;
            #pragma unroll
            for (int nt = 0; nt < 2; nt++) {
                int col  = ncol + 8 * nt + 2 * tg;
                int row0 = 16 * rh + gr;
                *reinterpret_cast<float2*>(&gp[(size_t)row0 * HID + col]) =
                    make_float2(acc[nt][0], acc[nt][1]);
                *reinterpret_cast<float2*>(&gp[(size_t)(row0 + 8) * HID + col]) =
                    make_float2(acc[nt][2], acc[nt][3]);
            }
        }
        __syncthreads();
        if (tid == 0) red_release(&g_flag[bid * FSTRIDE]);   // flag = t+1
    }

    // ---- Post-loop: all staged h_{T-1}; write last slice + tail ----
    if (wid < 4) {
        const unsigned* a = &g_flag[(wid * 32 + lane) * FSTRIDE];
        int spins = 0;
        bool done = false;
        while (true) {
            if (!done) done = (ld_relaxed(a) >= (unsigned)T_STEPS);
            if (__ballot_sync(0xffffffffu, !done) == 0) break;
            if (++spins > 8192) __nanosleep(64);
        }
        asm volatile("fence.acq_rel.gpu;" ::: "memory");
    }
    __syncthreads();
    if (owned) {
        *reinterpret_cast<float4*>(&out[(size_t)(T_STEPS - 1) * BH + my_off]) = saved;
        *reinterpret_cast<float4*>(&out[(size_t)T_STEPS * BH + my_off]) = saved;
    }

    // ---- Reset flags for graph replays ----
    __syncthreads();
    if (tid == 0) {
        unsigned d = atomicAdd(&g_done, 1u);
        if (d == (unsigned)(gridDim.x - 1)) {
            for (int i = 0; i < SC_BLOCKS; i++) g_flag[i * FSTRIDE] = 0;
            g_done = 0;
            __threadfence();
        }
    }
}

// ============================================================
extern "C" void kernel_launch(void* const* d_in, const int* in_sizes, int n_in,
                              void* d_out, int out_size) {
    const float* X    = (const float*)d_in[0];
    const float* W_xh = (const float*)d_in[1];
    const float* W_hh = (const float*)d_in[2];
    const float* b_h  = (const float*)d_in[3];
    float* out = (float*)d_out;

    {
        dim3 grid(HID / 64, (T_STEPS * BATCH) / 128);
        xp_gemm_tf32<<<grid, 256>>>(X, W_xh, b_h, out);
    }
    rnn_scan<<<SC_BLOCKS, 512>>>(W_hh, out);
}

// round 12
// speedup vs baseline: 2.4232x; 1.0619x over previous
#include <cuda_runtime.h>
#include <math.h>
#include <stdint.h>

#define T_STEPS 512
#define BATCH   64
#define IN_DIM  1024
#define HID     1024
#define BH      (BATCH * HID)          // 65536

// ---------- helpers ----------
__device__ __forceinline__ uint32_t f2tf32(float f) {
    uint32_t r;
    asm("cvt.rna.tf32.f32 %0, %1;" : "=r"(r) : "f"(f));
    return r;
}

__device__ __forceinline__ float tanh_fast(float x) {
    float y;
    asm("tanh.approx.f32 %0, %1;" : "=f"(y) : "f"(x));
    return y;
}

__device__ __forceinline__ void mma_tf32(float c[4], const uint32_t a[4], const uint32_t b[2]) {
    asm("mma.sync.aligned.m16n8k8.row.col.f32.tf32.tf32.f32 "
        "{%0,%1,%2,%3}, {%4,%5,%6,%7}, {%8,%9}, {%0,%1,%2,%3};\n"
        : "+f"(c[0]), "+f"(c[1]), "+f"(c[2]), "+f"(c[3])
        : "r"(a[0]), "r"(a[1]), "r"(a[2]), "r"(a[3]), "r"(b[0]), "r"(b[1]));
}

__device__ __forceinline__ unsigned ld_relaxed(const unsigned* p) {
    unsigned v;
    asm volatile("ld.relaxed.gpu.global.u32 %0, [%1];" : "=r"(v) : "l"(p) : "memory");
    return v;
}

__device__ __forceinline__ void red_release(unsigned* p) {
    asm volatile("red.release.gpu.global.add.u32 [%0], %1;" :: "l"(p), "r"(1u) : "memory");
}

__device__ __forceinline__ uint32_t smem_u32(const void* p) {
    return (uint32_t)__cvta_generic_to_shared(p);
}

__device__ __forceinline__ void cp_async16(uint32_t dst, const void* src) {
    asm volatile("cp.async.ca.shared.global [%0], [%1], 16;\n" :: "r"(dst), "l"(src));
}

__device__ __forceinline__ void cp_commit() {
    asm volatile("cp.async.commit_group;\n" ::);
}

template <int N>
__device__ __forceinline__ void cp_wait() {
    asm volatile("cp.async.wait_group %0;\n" :: "n"(N));
}

// ============================================================
// Kernel 1: Xp = X @ W_xh + b — cp.async double-buffered TF32 GEMM.
// Block 128m x 128n, BK=16, 256 thr = 8 warps (4m x 2n),
// warp tile 32m x 64n = 2 m16 x 8 n8. cvt.rna at fragment read.
// ============================================================
#define XP_AS 20    // 16 + 4 pad (words); row stride 80 B (16B multiple)
#define XP_BS 136   // 128 + 8 pad (words); row stride 544 B (16B multiple)

__global__ __launch_bounds__(256) void xp_gemm_tf32(const float* __restrict__ A,
                                                    const float* __restrict__ B,
                                                    const float* __restrict__ bias,
                                                    float* __restrict__ C) {
    __shared__ __align__(16) float As[2][128][XP_AS];
    __shared__ __align__(16) float Bs[2][16][XP_BS];
    __shared__ float biasS[128];

    const int bm  = blockIdx.y * 128;
    const int bn  = blockIdx.x * 128;
    const int tid = threadIdx.x;
    const int wid = tid >> 5;
    const int lane = tid & 31;
    const int gr  = lane >> 2;
    const int tg  = lane & 3;
    const int m_warp = wid & 3;        // 0..3 -> 32 rows each
    const int n_warp = wid >> 2;       // 0..1 -> 64 cols each

    if (tid < 128) biasS[tid] = bias[bn + tid];

    // A-chunk: 128 rows x 16 k = 512 float4; B-chunk: 16 k x 128 n = 512 float4.
    const int a_row = tid >> 1;              // with j: idx = tid + j*256 -> row=idx>>2
    (void)a_row;

    auto load_chunk = [&](int c, int buf) {
        const int k0 = c * 16;
        #pragma unroll
        for (int j = 0; j < 2; j++) {
            int idx = tid + j * 256;         // 0..511
            int row = idx >> 2;              // 0..127
            int kq  = (idx & 3) * 4;         // 0,4,8,12
            cp_async16(smem_u32(&As[buf][row][kq]),
                       &A[(size_t)(bm + row) * IN_DIM + k0 + kq]);
        }
        #pragma unroll
        for (int j = 0; j < 2; j++) {
            int idx = tid + j * 256;         // 0..511
            int kk  = idx >> 5;              // 0..15
            int nq  = (idx & 31) * 4;        // 0..124
            cp_async16(smem_u32(&Bs[buf][kk][nq]),
                       &B[(size_t)(k0 + kk) * HID + bn + nq]);
        }
        cp_commit();
    };

    float acc[2][8][4] = {};   // [m16][n8][frag]

    load_chunk(0, 0);

    for (int c = 0; c < IN_DIM / 16; c++) {
        const int buf = c & 1;
        if (c < IN_DIM / 16 - 1) {
            load_chunk(c + 1, (c + 1) & 1);
            cp_wait<1>();
        } else {
            cp_wait<0>();
        }
        __syncthreads();

        #pragma unroll
        for (int k8i = 0; k8i < 2; k8i++) {
            const int k8 = k8i * 8;
            uint32_t bf[8][2];
            #pragma unroll
            for (int nt = 0; nt < 8; nt++) {
                int nn = n_warp * 64 + nt * 8 + gr;
                bf[nt][0] = f2tf32(Bs[buf][k8 + tg][nn]);
                bf[nt][1] = f2tf32(Bs[buf][k8 + tg + 4][nn]);
            }
            #pragma unroll
            for (int mt = 0; mt < 2; mt++) {
                int mb = m_warp * 32 + mt * 16;
                uint32_t af[4];
                af[0] = f2tf32(As[buf][mb + gr][k8 + tg]);
                af[1] = f2tf32(As[buf][mb + gr + 8][k8 + tg]);
                af[2] = f2tf32(As[buf][mb + gr][k8 + tg + 4]);
                af[3] = f2tf32(As[buf][mb + gr + 8][k8 + tg + 4]);
                #pragma unroll
                for (int nt = 0; nt < 8; nt++)
                    mma_tf32(acc[mt][nt], af, bf[nt]);
            }
        }
        __syncthreads();
    }

    #pragma unroll
    for (int mt = 0; mt < 2; mt++) {
        #pragma unroll
        for (int nt = 0; nt < 8; nt++) {
            int colL = n_warp * 64 + nt * 8 + 2 * tg;
            int row0 = bm + m_warp * 32 + mt * 16 + gr;
            float2 v0, v1;
            v0.x = acc[mt][nt][0] + biasS[colL];
            v0.y = acc[mt][nt][1] + biasS[colL + 1];
            v1.x = acc[mt][nt][2] + biasS[colL];
            v1.y = acc[mt][nt][3] + biasS[colL + 1];
            *reinterpret_cast<float2*>(&C[(size_t)row0 * HID + bn + colL]) = v0;
            *reinterpret_cast<float2*>(&C[(size_t)(row0 + 8) * HID + bn + colL]) = v1;
        }
    }
}

// ============================================================
// Persistent scan v4 — fused-reduce split-K, ONE global round/step.
// (Byte-identical to round 11 — validated WIN.)
// ============================================================
#define SC_BLOCKS 128
#define HS_STRIDE 144
#define FSTRIDE   32

__device__ float    g_part[2 * 8 * BH];    // 4 MB, parity-buffered partials
__device__ unsigned g_flag[SC_BLOCKS * FSTRIDE];
__device__ unsigned g_done = 0;

__global__ __launch_bounds__(512, 1) void rnn_scan(const float* __restrict__ W,
                                                   float* __restrict__ out) {
    __shared__ uint32_t hs[16][HS_STRIDE];

    const int tid  = threadIdx.x;
    const int bid  = blockIdx.x;
    const int ks   = bid >> 4;
    const int nb   = (bid >> 2) & 3;
    const int rh   = bid & 3;
    const int wid  = tid >> 5;
    const int lane = tid & 31;
    const int gr   = lane >> 2;
    const int tg   = lane & 3;

    uint32_t bfr[8][2][2][2];
    {
        const int ncol = 256 * nb + 16 * wid;
        #pragma unroll
        for (int u = 0; u < 8; u++)
            #pragma unroll
            for (int p = 0; p < 2; p++)
                #pragma unroll
                for (int nt = 0; nt < 2; nt++) {
                    int n  = ncol + 8 * nt + gr;
                    int kk = 128 * ks + 16 * u + 4 * tg + 2 * p;
                    bfr[u][p][nt][0] = f2tf32(W[(size_t)kk * HID + n]);
                    bfr[u][p][nt][1] = f2tf32(W[(size_t)(kk + 1) * HID + n]);
                }
    }

    const int r   = tid >> 5;
    const int c4  = (tid & 31) * 4;
    const int g_row = 16 * rh + r;
    const size_t my_off = (size_t)g_row * HID + 128 * ks + c4;
    const bool owned = ((r >> 2) == nb);
    float4 saved;

    for (int t = 0; t < T_STEPS; t++) {
        float* o = out + (size_t)t * BH;

        if (t > 0) {
            if (wid < 4) {
                const unsigned* a = &g_flag[(wid * 32 + lane) * FSTRIDE];
                int spins = 0;
                bool done = false;
                while (true) {
                    if (!done) done = (ld_relaxed(a) >= (unsigned)t);
                    if (__ballot_sync(0xffffffffu, !done) == 0) break;
                    if (++spins > 8192) __nanosleep(64);
                }
                asm volatile("fence.acq_rel.gpu;" ::: "memory");
            }
            __syncthreads();

            if (owned)
                *reinterpret_cast<float4*>(&out[(size_t)(t - 1) * BH + my_off]) = saved;
        }

        {
            float4 s = *reinterpret_cast<const float4*>(&o[my_off]);
            if (t > 0) {
                const float* pb = g_part + (size_t)(t & 1) * (8 * BH);
                #pragma unroll
                for (int kk = 0; kk < 8; kk++) {
                    float4 p = *reinterpret_cast<const float4*>(
                        &pb[(size_t)kk * BH + my_off]);
                    s.x += p.x; s.y += p.y; s.z += p.z; s.w += p.w;
                }
            }
            s.x = tanh_fast(s.x); s.y = tanh_fast(s.y);
            s.z = tanh_fast(s.z); s.w = tanh_fast(s.w);
            if (owned) saved = s;
            uint4 w = make_uint4(f2tf32(s.x), f2tf32(s.y), f2tf32(s.z), f2tf32(s.w));
            *reinterpret_cast<uint4*>(&hs[r][c4]) = w;
        }
        __syncthreads();

        if (t < T_STEPS - 1) {
            float acc[2][4] = {};
            #pragma unroll
            for (int u = 0; u < 8; u++) {
                const int kc = 16 * u + 4 * tg;
                uint4 va = *reinterpret_cast<const uint4*>(&hs[gr][kc]);
                uint4 vb = *reinterpret_cast<const uint4*>(&hs[gr + 8][kc]);
                uint32_t afA[4] = {va.x, vb.x, va.y, vb.y};
                uint32_t afB[4] = {va.z, vb.z, va.w, vb.w};
                mma_tf32(acc[0], afA, bfr[u][0][0]);
                mma_tf32(acc[1], afA, bfr[u][0][1]);
                mma_tf32(acc[0], afB, bfr[u][1][0]);
                mma_tf32(acc[1], afB, bfr[u][1][1]);
            }
            float* gp = g_part + (size_t)((t + 1) & 1) * (8 * BH) + (size_t)ks * BH;
            const int ncol = 256 * nb + 16 * wid;
            #pragma unroll
            for (int nt = 0; nt < 2; nt++) {
                int col  = ncol + 8 * nt + 2 * tg;
                int row0 = 16 * rh + gr;
                *reinterpret_cast<float2*>(&gp[(size_t)row0 * HID + col]) =
                    make_float2(acc[nt][0], acc[nt][1]);
                *reinterpret_cast<float2*>(&gp[(size_t)(row0 + 8) * HID + col]) =
                    make_float2(acc[nt][2], acc[nt][3]);
            }
        }
        __syncthreads();
        if (tid == 0) red_release(&g_flag[bid * FSTRIDE]);
    }

    if (wid < 4) {
        const unsigned* a = &g_flag[(wid * 32 + lane) * FSTRIDE];
        int spins = 0;
        bool done = false;
        while (true) {
            if (!done) done = (ld_relaxed(a) >= (unsigned)T_STEPS);
            if (__ballot_sync(0xffffffffu, !done) == 0) break;
            if (++spins > 8192) __nanosleep(64);
        }
        asm volatile("fence.acq_rel.gpu;" ::: "memory");
    }
    __syncthreads();
    if (owned) {
        *reinterpret_cast<float4*>(&out[(size_t)(T_STEPS - 1) * BH + my_off]) = saved;
        *reinterpret_cast<float4*>(&out[(size_t)T_STEPS * BH + my_off]) = saved;
    }

    __syncthreads();
    if (tid == 0) {
        unsigned d = atomicAdd(&g_done, 1u);
        if (d == (unsigned)(gridDim.x - 1)) {
            for (int i = 0; i < SC_BLOCKS; i++) g_flag[i * FSTRIDE] = 0;
            g_done = 0;
            __threadfence();
        }
    }
}

// ============================================================
extern "C" void kernel_launch(void* const* d_in, const int* in_sizes, int n_in,
                              void* d_out, int out_size) {
    const float* X    = (const float*)d_in[0];
    const float* W_xh = (const float*)d_in[1];
    const float* W_hh = (const float*)d_in[2];
    const float* b_h  = (const float*)d_in[3];
    float* out = (float*)d_out;

    {
        dim3 grid(HID / 128, (T_STEPS * BATCH) / 128);
        xp_gemm_tf32<<<grid, 256>>>(X, W_xh, b_h, out);
    }
    rnn_scan<<<SC_BLOCKS, 512>>>(W_hh, out);
}